// round 12
// baseline (speedup 1.0000x reference)
#include <cuda_runtime.h>
#include <cuda_bf16.h>
#include <cstdint>

#define Nn     8192
#define FIN    512
#define FOUT   256
#define LALPHA 0.2f
#define M_TILE 128
#define KC     64
#define NBLK   (Nn / M_TILE)          // 64 row blocks
#define CPB    (Nn / KC)              // 128 chunks per row block
#define TOTSLOT (NBLK * CPB)          // 8192
#define NCTA   148

// attn smem layout
#define WT_STRIDE 68                  // WhT tile k-stride (words), conflict-free
#define ADJ_STRIDE 68                 // adj tile row stride (words)
#define WHTILE_WORDS (FOUT * WT_STRIDE)       // 256*68 = 17408
#define ADJTILE_WORDS (M_TILE * ADJ_STRIDE)   // 8704
#define SM_ADJ (2 * WHTILE_WORDS)             // 34816
#define SM_FBD (SM_ADJ + 2 * ADJTILE_WORDS)   // 52224
#define SMEM_DYN ((SM_FBD + 2 * 192) * 4)     // 210432 B

// gemm_wh_mma tiles (unchanged layout)
#define GW_STRIDE 264
#define GWTILE_WORDS (KC * GW_STRIDE)         // 16896
#define GM      64
#define HS      68
#define HS_WORDS (GM * HS)                    // 4352
#define GSM_A   (2 * HS_WORDS + 2 * GWTILE_WORDS)
#define GSMEM_DYN ((GSM_A + 512) * 4)         // 172032 B

// ---------------- scratch (device globals: allowed) ----------------
__device__ float d_WhrT[(size_t)FOUT * Nn];          // 8 MB tf32-rounded, [n][j]
__device__ float d_Wr[(size_t)FIN * FOUT];           // 512 KB tf32-rounded W
__device__ float d_f1[Nn];
__device__ float d_f2[Nn];
__device__ float d_A[Nn];
__device__ float d_C[Nn];
__device__ float d_B[Nn];
__device__ float d_D[Nn];
__device__ int   d_gmaxkey;
__device__ float d_num[(size_t)Nn * FOUT];           // 8 MB (atomic accum)
__device__ float d_ssum[Nn];

__device__ __forceinline__ uint32_t tf32_bits(float x) {
    uint32_t r; asm("cvt.rna.tf32.f32 %0, %1;" : "=r"(r) : "f"(x)); return r;
}
__device__ __forceinline__ void mma_tf32(float* d, uint32_t a0, uint32_t a1,
                                         uint32_t a2, uint32_t a3,
                                         uint32_t b0, uint32_t b1) {
    asm volatile(
        "mma.sync.aligned.m16n8k8.row.col.f32.tf32.tf32.f32 "
        "{%0,%1,%2,%3}, {%4,%5,%6,%7}, {%8,%9}, {%0,%1,%2,%3};"
        : "+f"(d[0]), "+f"(d[1]), "+f"(d[2]), "+f"(d[3])
        : "r"(a0), "r"(a1), "r"(a2), "r"(a3), "r"(b0), "r"(b1));
}
__device__ __forceinline__ uint32_t smem_u32(const void* p) {
    uint32_t a;
    asm("{ .reg .u64 t; cvta.to.shared.u64 t, %1; cvt.u32.u64 %0, t; }"
        : "=r"(a) : "l"(p));
    return a;
}
__device__ __forceinline__ void cp_async16(uint32_t sa, const void* g) {
    asm volatile("cp.async.ca.shared.global [%0], [%1], 16;" :: "r"(sa), "l"(g) : "memory");
}
__device__ __forceinline__ void cp_commit() {
    asm volatile("cp.async.commit_group;" ::: "memory");
}
template <int N> __device__ __forceinline__ void cp_wait() {
    asm volatile("cp.async.wait_group %0;" :: "n"(N) : "memory");
}

// ---------------- init: zero accumulators + round W ----------------
__global__ void init_kernel(const float* __restrict__ W) {
    if (blockIdx.x == 0 && threadIdx.x == 0) d_gmaxkey = (int)0x80000000;
    size_t i = ((size_t)blockIdx.x * 256 + threadIdx.x) * 4;
    *(float4*)&d_num[i] = make_float4(0.f, 0.f, 0.f, 0.f);
    if (i < Nn)
        *(float4*)&d_ssum[i] = make_float4(0.f, 0.f, 0.f, 0.f);
    if (i < (size_t)FIN * FOUT) {
        float4 v = *(const float4*)&W[i];
        float4 o;
        o.x = __uint_as_float(tf32_bits(v.x));
        o.y = __uint_as_float(tf32_bits(v.y));
        o.z = __uint_as_float(tf32_bits(v.z));
        o.w = __uint_as_float(tf32_bits(v.w));
        *(float4*)&d_Wr[i] = o;
    }
}

// ---------------- Wh = h @ W via mma.sync tf32 (+ fused f1/f2/max) ----------------
__device__ __forceinline__ void stage_g(uint32_t sbase, const float* __restrict__ h,
                                        int i0, int c, int t) {
    int buf = c & 1;
    int k0  = c * KC;
    uint32_t hb = sbase + (uint32_t)(buf * HS_WORDS * 4);
#pragma unroll
    for (int u = 0; u < 4; u++) {
        int f = u * 256 + t;
        int row = f >> 4, seg = (f & 15) << 2;
        cp_async16(hb + (uint32_t)((row * HS + seg) * 4),
                   &h[(size_t)(i0 + row) * FIN + k0 + seg]);
    }
    uint32_t wb = sbase + (uint32_t)((2 * HS_WORDS + buf * GWTILE_WORDS) * 4);
#pragma unroll
    for (int u = 0; u < 16; u++) {
        int f = u * 256 + t;
        int row = f >> 6, c4 = (f & 63) << 2;
        cp_async16(wb + (uint32_t)((row * GW_STRIDE + c4) * 4),
                   &d_Wr[(size_t)(k0 + row) * FOUT + c4]);
    }
}

__global__ void __launch_bounds__(256, 1) gemm_wh_mma(const float* __restrict__ h,
                                                      const float* __restrict__ a) {
    extern __shared__ float gsm[];
    uint32_t sbase = smem_u32(gsm);
    float* as = gsm + GSM_A;   // a1[256] then a2[256]

    int t    = threadIdx.x;
    int lane = t & 31, wid = t >> 5;
    int mstrip = wid >> 1, nhalf = wid & 1;
    int gID = lane >> 2, tID = lane & 3;
    int r0t = mstrip * 16 + gID;
    int i0  = blockIdx.x * GM;

    if (t < 128) *(float4*)&as[t * 4] = *(const float4*)&a[t * 4];

    float acc[16][4];
#pragma unroll
    for (int n = 0; n < 16; n++)
#pragma unroll
        for (int u = 0; u < 4; u++) acc[n][u] = 0.f;

    stage_g(sbase, h, i0, 0, t);
    cp_commit();

    for (int c = 0; c < FIN / KC; c++) {
        int buf = c & 1;
        cp_wait<0>();
        __syncthreads();
        if (c + 1 < FIN / KC) {
            stage_g(sbase, h, i0, c + 1, t);
            cp_commit();
        }
        const float* hs = gsm + buf * HS_WORDS;
        const float* Wb = gsm + 2 * HS_WORDS + buf * GWTILE_WORDS;
#pragma unroll
        for (int k = 0; k < 8; k++) {
            int kc = tID + 8 * k;
            uint32_t a0 = tf32_bits(hs[(r0t)     * HS + kc]);
            uint32_t a1 = tf32_bits(hs[(r0t + 8) * HS + kc]);
            uint32_t a2 = tf32_bits(hs[(r0t)     * HS + kc + 4]);
            uint32_t a3 = tf32_bits(hs[(r0t + 8) * HS + kc + 4]);
            int krow = k * 8 + tID;
#pragma unroll
            for (int n = 0; n < 16; n++) {
                int n0 = nhalf * 128 + n * 8 + gID;
                uint32_t b0 = __float_as_uint(Wb[krow * GW_STRIDE + n0]);
                uint32_t b1 = __float_as_uint(Wb[(krow + 4) * GW_STRIDE + n0]);
                mma_tf32(acc[n], a0, a1, a2, a3, b0, b1);
            }
        }
        __syncthreads();
    }

    // epilogue: tf32-rounded WhrT (transposed [n][j]) + fused f1/f2 + block max(f2)
    float s1a = 0.f, s2a = 0.f, s1b = 0.f, s2b = 0.f;
    int cb = nhalf * 128 + tID * 2;
    int ia  = i0 + r0t, ib2 = i0 + r0t + 8;
#pragma unroll
    for (int n = 0; n < 16; n++) {
        int cc = cb + n * 8;
        d_WhrT[(size_t)cc * Nn + ia]       = __uint_as_float(tf32_bits(acc[n][0]));
        d_WhrT[(size_t)(cc + 1) * Nn + ia] = __uint_as_float(tf32_bits(acc[n][1]));
        d_WhrT[(size_t)cc * Nn + ib2]       = __uint_as_float(tf32_bits(acc[n][2]));
        d_WhrT[(size_t)(cc + 1) * Nn + ib2] = __uint_as_float(tf32_bits(acc[n][3]));
        float a10 = as[cc], a11 = as[cc + 1];
        float a20 = as[256 + cc], a21 = as[256 + cc + 1];
        s1a += acc[n][0] * a10 + acc[n][1] * a11;
        s2a += acc[n][0] * a20 + acc[n][1] * a21;
        s1b += acc[n][2] * a10 + acc[n][3] * a11;
        s2b += acc[n][2] * a20 + acc[n][3] * a21;
    }
#pragma unroll
    for (int o = 1; o <= 2; o <<= 1) {
        s1a += __shfl_xor_sync(0xffffffffu, s1a, o);
        s2a += __shfl_xor_sync(0xffffffffu, s2a, o);
        s1b += __shfl_xor_sync(0xffffffffu, s1b, o);
        s2b += __shfl_xor_sync(0xffffffffu, s2b, o);
    }
    if (nhalf == 1 && tID == 0) {
        gsm[r0t]       = s1a;  gsm[64 + r0t]      = s2a;
        gsm[r0t + 8]   = s1b;  gsm[64 + r0t + 8]  = s2b;
    }
    __syncthreads();
    float mx = -3.0e38f;
    if (nhalf == 0 && tID == 0) {
        float f1t = s1a + gsm[r0t],     f2t = s2a + gsm[64 + r0t];
        float f1u = s1b + gsm[r0t + 8], f2u = s2b + gsm[64 + r0t + 8];
        d_f1[i0 + r0t]     = f1t;  d_f2[i0 + r0t]     = f2t;
        d_f1[i0 + r0t + 8] = f1u;  d_f2[i0 + r0t + 8] = f2u;
        mx = fmaxf(f2t, f2u);
    }
#pragma unroll
    for (int o = 16; o; o >>= 1)
        mx = fmaxf(mx, __shfl_xor_sync(0xffffffffu, mx, o));
    if (lane == 0) gsm[128 + wid] = mx;
    __syncthreads();
    if (t == 0) {
        float m = gsm[128];
#pragma unroll
        for (int w = 1; w < 8; w++) m = fmaxf(m, gsm[128 + w]);
        int b = __float_as_int(m);
        int key = b >= 0 ? b : (b ^ 0x7fffffff);
        atomicMax(&d_gmaxkey, key);
    }
}

// ---------------- factorized softmax weights ----------------
__global__ void pexp_kernel() {
    int i = blockIdx.x * 256 + threadIdx.x;
    int kk = d_gmaxkey;
    float gm = __int_as_float(kk >= 0 ? kk : (kk ^ 0x7fffffff));
    float f1 = d_f1[i], f2 = d_f2[i];
    float u  = f1 + gm;
    float m  = u > 0.f ? u : LALPHA * u;
    d_A[i] = __expf(u - m);
    d_C[i] = __expf(LALPHA * u - m);
    float v = f2 - gm;
    d_B[i] = __expf(v);
    d_D[i] = __expf(LALPHA * v);
}

// ---------------- staging helpers (cp.async) ----------------
__device__ __forceinline__ void stage_slot(uint32_t sbase, const int* adj,
                                           int s, int t) {
    int buf = s & 1;
    int ib  = s >> 7;
    int jg  = (s & (CPB - 1)) * KC;
    // WhT tile [256 n][64 k], stride 68 words
    uint32_t wb = sbase + (uint32_t)(buf * WHTILE_WORDS * 4);
#pragma unroll
    for (int u = 0; u < 8; u++) {
        int f = u * 512 + t;                  // 0..4095
        int row = f >> 4, seg = (f & 15) << 2;
        cp_async16(wb + (uint32_t)((row * WT_STRIDE + seg) * 4),
                   &d_WhrT[(size_t)row * Nn + jg + seg]);
    }
    uint32_t ab = sbase + (uint32_t)((SM_ADJ + buf * ADJTILE_WORDS) * 4);
    const int* abase = adj + (size_t)ib * M_TILE * Nn + jg;
#pragma unroll
    for (int u = 0; u < 4; u++) {
        int f = u * 512 + t;
        int row = f >> 4, seg = (f & 15) << 2;
        cp_async16(ab + (uint32_t)((row * ADJ_STRIDE + seg) * 4),
                   abase + (size_t)row * Nn + seg);
    }
    if (t < 48) {
        uint32_t fb = sbase + (uint32_t)((SM_FBD + buf * 192 + t * 4) * 4);
        const float* src = (t < 16) ? &d_f2[jg + t * 4]
                         : (t < 32) ? &d_B[jg + (t - 16) * 4]
                                    : &d_D[jg + (t - 32) * 4];
        cp_async16(fb, src);
    }
}

// ---------------- fused attention @ Wh via mma.sync tf32 ----------------
// 148 CTAs x 512 threads = 16 warps: 4 m-strips (32 rows) x 4 n-quarters (64 cols).
// Warp tile 32x64: 2 m-tiles x 8 n-tiles; B-frags conflict-free from WhT tile.
__global__ void __launch_bounds__(512, 1) attn_mma(const int* __restrict__ adj) {
    extern __shared__ float sm[];
    uint32_t sbase = smem_u32(sm);

    int t    = threadIdx.x;
    int lane = t & 31, wid = t >> 5;
    int mstrip = wid >> 2, nq = wid & 3;
    int gID = lane >> 2, tID = lane & 3;
    int mr  = mstrip * 32;

    int s0 = (int)(((long long)blockIdx.x * TOTSLOT) / NCTA);
    int s1 = (int)(((long long)(blockIdx.x + 1) * TOTSLOT) / NCTA);

    float acc[8][2][4];
#pragma unroll
    for (int n = 0; n < 8; n++)
#pragma unroll
        for (int mt = 0; mt < 2; mt++)
#pragma unroll
            for (int u = 0; u < 4; u++) acc[n][mt][u] = 0.f;
    float ssum[4] = {0.f, 0.f, 0.f, 0.f};

    float f1c[4], Ac[4], Cc[4];
    int cur_ib = -1;

    stage_slot(sbase, adj, s0, t);
    cp_commit();

    for (int s = s0; s < s1; s++) {
        int ib = s >> 7;
        int buf = s & 1;

        if (ib != cur_ib) {
            if (cur_ib >= 0) {
                // flush partials for cur_ib
                int base = cur_ib * M_TILE;
#pragma unroll
                for (int q = 0; q < 4; q++) {
                    float sv = ssum[q];
                    sv += __shfl_xor_sync(0xffffffffu, sv, 1);
                    sv += __shfl_xor_sync(0xffffffffu, sv, 2);
                    if (tID == 0 && nq == 0)
                        atomicAdd(&d_ssum[base + mr + q * 8 + gID], sv);
                    ssum[q] = 0.f;
                }
                float* np = &d_num[(size_t)base * FOUT];
#pragma unroll
                for (int n = 0; n < 8; n++) {
                    int cc = nq * 64 + n * 8 + tID * 2;
#pragma unroll
                    for (int mt = 0; mt < 2; mt++) {
                        int ra = mr + mt * 16 + gID;
                        atomicAdd(&np[(size_t)ra * FOUT + cc],           acc[n][mt][0]);
                        atomicAdd(&np[(size_t)ra * FOUT + cc + 1],       acc[n][mt][1]);
                        atomicAdd(&np[(size_t)(ra + 8) * FOUT + cc],     acc[n][mt][2]);
                        atomicAdd(&np[(size_t)(ra + 8) * FOUT + cc + 1], acc[n][mt][3]);
                        acc[n][mt][0] = 0.f; acc[n][mt][1] = 0.f;
                        acc[n][mt][2] = 0.f; acc[n][mt][3] = 0.f;
                    }
                }
            }
            int base = ib * M_TILE;
#pragma unroll
            for (int q = 0; q < 4; q++) {
                int r = base + mr + q * 8 + gID;
                f1c[q] = d_f1[r];
                Ac[q]  = d_A[r];
                Cc[q]  = d_C[r];
            }
            cur_ib = ib;
        }

        cp_wait<0>();
        __syncthreads();

        if (s + 1 < s1) {
            stage_slot(sbase, adj, s + 1, t);
            cp_commit();
        }

        const float* Wb   = sm + buf * WHTILE_WORDS;                 // [n][68]
        const int*   adjS = (const int*)(sm + SM_ADJ + buf * ADJTILE_WORDS);
        const float* fbd  = sm + SM_FBD + buf * 192;

#pragma unroll
        for (int k = 0; k < 8; k++) {
            int j0 = tID + 8 * k, j1 = j0 + 4;
            float f20 = fbd[j0], B0 = fbd[64 + j0], D0 = fbd[128 + j0];
            float f21 = fbd[j1], B1 = fbd[64 + j1], D1 = fbd[128 + j1];
            uint32_t afr[2][4];
#pragma unroll
            for (int mt = 0; mt < 2; mt++) {
                int ra = mr + mt * 16 + gID;
                int ad00 = adjS[ra * ADJ_STRIDE + j0];
                int ad10 = adjS[(ra + 8) * ADJ_STRIDE + j0];
                int ad01 = adjS[ra * ADJ_STRIDE + j1];
                int ad11 = adjS[(ra + 8) * ADJ_STRIDE + j1];
                float f1x = f1c[2 * mt],     Ax = Ac[2 * mt],     Cx = Cc[2 * mt];
                float f1y = f1c[2 * mt + 1], Ay = Ac[2 * mt + 1], Cy = Cc[2 * mt + 1];
                float e00 = f1x + f20, e10 = f1y + f20;
                float e01 = f1x + f21, e11 = f1y + f21;
                float p00 = (ad00 > 0) ? (e00 > 0.f ? Ax * B0 : Cx * D0) : 0.f;
                float p10 = (ad10 > 0) ? (e10 > 0.f ? Ay * B0 : Cy * D0) : 0.f;
                float p01 = (ad01 > 0) ? (e01 > 0.f ? Ax * B1 : Cx * D1) : 0.f;
                float p11 = (ad11 > 0) ? (e11 > 0.f ? Ay * B1 : Cy * D1) : 0.f;
                if (nq == 0) {
                    ssum[2 * mt]     += p00 + p01;
                    ssum[2 * mt + 1] += p10 + p11;
                }
                afr[mt][0] = tf32_bits(p00); afr[mt][1] = tf32_bits(p10);
                afr[mt][2] = tf32_bits(p01); afr[mt][3] = tf32_bits(p11);
            }
            int krow = k * 8 + tID;
#pragma unroll
            for (int n = 0; n < 8; n++) {
                int n0 = nq * 64 + n * 8 + gID;
                uint32_t b0 = __float_as_uint(Wb[n0 * WT_STRIDE + krow]);
                uint32_t b1 = __float_as_uint(Wb[n0 * WT_STRIDE + krow + 4]);
                mma_tf32(acc[n][0], afr[0][0], afr[0][1], afr[0][2], afr[0][3], b0, b1);
                mma_tf32(acc[n][1], afr[1][0], afr[1][1], afr[1][2], afr[1][3], b0, b1);
            }
        }
    }

    // final flush
    {
        int base = cur_ib * M_TILE;
#pragma unroll
        for (int q = 0; q < 4; q++) {
            float sv = ssum[q];
            sv += __shfl_xor_sync(0xffffffffu, sv, 1);
            sv += __shfl_xor_sync(0xffffffffu, sv, 2);
            if (tID == 0 && nq == 0)
                atomicAdd(&d_ssum[base + mr + q * 8 + gID], sv);
        }
        float* np = &d_num[(size_t)base * FOUT];
#pragma unroll
        for (int n = 0; n < 8; n++) {
            int cc = nq * 64 + n * 8 + tID * 2;
#pragma unroll
            for (int mt = 0; mt < 2; mt++) {
                int ra = mr + mt * 16 + gID;
                atomicAdd(&np[(size_t)ra * FOUT + cc],           acc[n][mt][0]);
                atomicAdd(&np[(size_t)ra * FOUT + cc + 1],       acc[n][mt][1]);
                atomicAdd(&np[(size_t)(ra + 8) * FOUT + cc],     acc[n][mt][2]);
                atomicAdd(&np[(size_t)(ra + 8) * FOUT + cc + 1], acc[n][mt][3]);
            }
        }
    }
}

// ---------------- normalize + ELU (vectorized) ----------------
__global__ void elu_kernel(float* __restrict__ out) {
    int idx = blockIdx.x * 256 + threadIdx.x;     // one float4 per thread
    int row = idx >> 6;                           // 64 float4 per row
    float s = d_ssum[row];
    float4 v = *(const float4*)&d_num[(size_t)idx * 4];
    float4 o;
    float x;
    x = v.x / s; o.x = x > 0.f ? x : expm1f(x);
    x = v.y / s; o.y = x > 0.f ? x : expm1f(x);
    x = v.z / s; o.z = x > 0.f ? x : expm1f(x);
    x = v.w / s; o.w = x > 0.f ? x : expm1f(x);
    *(float4*)&out[(size_t)idx * 4] = o;
}

extern "C" void kernel_launch(void* const* d_in, const int* in_sizes, int n_in,
                              void* d_out, int out_size) {
    const float* h   = (const float*)d_in[0];
    const int*   adj = (const int*)d_in[1];
    const float* W   = (const float*)d_in[2];
    const float* a   = (const float*)d_in[3];
    float* out = (float*)d_out;

    cudaFuncSetAttribute(attn_mma, cudaFuncAttributeMaxDynamicSharedMemorySize, SMEM_DYN);
    cudaFuncSetAttribute(gemm_wh_mma, cudaFuncAttributeMaxDynamicSharedMemorySize, GSMEM_DYN);

    init_kernel<<<(Nn * FOUT) / 1024, 256>>>(W);
    gemm_wh_mma<<<Nn / GM, 256, GSMEM_DYN>>>(h, a);
    pexp_kernel<<<Nn / 256, 256>>>();
    attn_mma<<<NCTA, 512, SMEM_DYN>>>(adj);
    elu_kernel<<<(Nn * FOUT) / 1024, 256>>>(out);
}

// round 13
// speedup vs baseline: 1.5139x; 1.5139x over previous
#include <cuda_runtime.h>
#include <cuda_fp16.h>
#include <cstdint>

#define Nn     8192
#define FIN    512
#define FOUT   256
#define LALPHA 0.2f
#define M_TILE 128
#define KC     64
#define NBLK   (Nn / M_TILE)          // 64 row blocks
#define CPB    (Nn / KC)              // 128 chunks per row block
#define TOTSLOT (NBLK * CPB)          // 8192
#define NCTA   148

// attn smem layout (words)
#define WT_STRIDE_H 72                // WhT half tile j-stride (halfs) = 36 words
#define WHTILE_WORDS (FOUT * (WT_STRIDE_H / 2))   // 256*36 = 9216
#define ADJ_STRIDE 68
#define ADJTILE_WORDS (M_TILE * ADJ_STRIDE)       // 8704
#define SM_ADJ (2 * WHTILE_WORDS)                 // 18432
#define SM_FBD (SM_ADJ + 2 * ADJTILE_WORDS)       // 35840
#define SMEM_DYN ((SM_FBD + 2 * 192) * 4)         // 144896 B

// gemm_wh_mma tiles
#define GW_STRIDE 264
#define GWTILE_WORDS (KC * GW_STRIDE)             // 16896
#define GM      64
#define HS      68
#define HS_WORDS (GM * HS)                        // 4352
#define GSM_A   (2 * HS_WORDS + 2 * GWTILE_WORDS)
#define GSMEM_DYN ((GSM_A + 512) * 4)             // 172032 B

// ---------------- scratch (device globals: allowed) ----------------
__device__ __half d_WhhT[(size_t)FOUT * Nn];         // 4 MB half, [n][j]
__device__ float d_Wr[(size_t)FIN * FOUT];           // tf32-rounded W
__device__ float d_f1[Nn];
__device__ float d_f2[Nn];
__device__ float d_A[Nn];
__device__ float d_C[Nn];
__device__ float d_B[Nn];
__device__ float d_D[Nn];
__device__ int   d_gmaxkey;
__device__ float d_num[(size_t)Nn * FOUT];           // 8 MB (atomic accum)
__device__ float d_ssum[Nn];

__device__ __forceinline__ uint32_t tf32_bits(float x) {
    uint32_t r; asm("cvt.rna.tf32.f32 %0, %1;" : "=r"(r) : "f"(x)); return r;
}
__device__ __forceinline__ void mma_tf32(float* d, uint32_t a0, uint32_t a1,
                                         uint32_t a2, uint32_t a3,
                                         uint32_t b0, uint32_t b1) {
    asm volatile(
        "mma.sync.aligned.m16n8k8.row.col.f32.tf32.tf32.f32 "
        "{%0,%1,%2,%3}, {%4,%5,%6,%7}, {%8,%9}, {%0,%1,%2,%3};"
        : "+f"(d[0]), "+f"(d[1]), "+f"(d[2]), "+f"(d[3])
        : "r"(a0), "r"(a1), "r"(a2), "r"(a3), "r"(b0), "r"(b1));
}
__device__ __forceinline__ void mma_f16(float* d, uint32_t a0, uint32_t a1,
                                        uint32_t a2, uint32_t a3,
                                        uint32_t b0, uint32_t b1) {
    asm volatile(
        "mma.sync.aligned.m16n8k16.row.col.f32.f16.f16.f32 "
        "{%0,%1,%2,%3}, {%4,%5,%6,%7}, {%8,%9}, {%0,%1,%2,%3};"
        : "+f"(d[0]), "+f"(d[1]), "+f"(d[2]), "+f"(d[3])
        : "r"(a0), "r"(a1), "r"(a2), "r"(a3), "r"(b0), "r"(b1));
}
__device__ __forceinline__ uint32_t smem_u32(const void* p) {
    uint32_t a;
    asm("{ .reg .u64 t; cvta.to.shared.u64 t, %1; cvt.u32.u64 %0, t; }"
        : "=r"(a) : "l"(p));
    return a;
}
__device__ __forceinline__ void cp_async16(uint32_t sa, const void* g) {
    asm volatile("cp.async.ca.shared.global [%0], [%1], 16;" :: "r"(sa), "l"(g) : "memory");
}
__device__ __forceinline__ void cp_commit() {
    asm volatile("cp.async.commit_group;" ::: "memory");
}
template <int N> __device__ __forceinline__ void cp_wait() {
    asm volatile("cp.async.wait_group %0;" :: "n"(N) : "memory");
}

// ---------------- init: zero accumulators + round W ----------------
__global__ void init_kernel(const float* __restrict__ W) {
    if (blockIdx.x == 0 && threadIdx.x == 0) d_gmaxkey = (int)0x80000000;
    size_t i = ((size_t)blockIdx.x * 256 + threadIdx.x) * 4;
    *(float4*)&d_num[i] = make_float4(0.f, 0.f, 0.f, 0.f);
    if (i < Nn)
        *(float4*)&d_ssum[i] = make_float4(0.f, 0.f, 0.f, 0.f);
    if (i < (size_t)FIN * FOUT) {
        float4 v = *(const float4*)&W[i];
        float4 o;
        o.x = __uint_as_float(tf32_bits(v.x));
        o.y = __uint_as_float(tf32_bits(v.y));
        o.z = __uint_as_float(tf32_bits(v.z));
        o.w = __uint_as_float(tf32_bits(v.w));
        *(float4*)&d_Wr[i] = o;
    }
}

// ---------------- Wh = h @ W via mma.sync tf32 (+ fused f1/f2/max) ----------------
__device__ __forceinline__ void stage_g(uint32_t sbase, const float* __restrict__ h,
                                        int i0, int c, int t) {
    int buf = c & 1;
    int k0  = c * KC;
    uint32_t hb = sbase + (uint32_t)(buf * HS_WORDS * 4);
#pragma unroll
    for (int u = 0; u < 4; u++) {
        int f = u * 256 + t;
        int row = f >> 4, seg = (f & 15) << 2;
        cp_async16(hb + (uint32_t)((row * HS + seg) * 4),
                   &h[(size_t)(i0 + row) * FIN + k0 + seg]);
    }
    uint32_t wb = sbase + (uint32_t)((2 * HS_WORDS + buf * GWTILE_WORDS) * 4);
#pragma unroll
    for (int u = 0; u < 16; u++) {
        int f = u * 256 + t;
        int row = f >> 6, c4 = (f & 63) << 2;
        cp_async16(wb + (uint32_t)((row * GW_STRIDE + c4) * 4),
                   &d_Wr[(size_t)(k0 + row) * FOUT + c4]);
    }
}

__global__ void __launch_bounds__(256, 1) gemm_wh_mma(const float* __restrict__ h,
                                                      const float* __restrict__ a) {
    extern __shared__ float gsm[];
    uint32_t sbase = smem_u32(gsm);
    float* as = gsm + GSM_A;   // a1[256] then a2[256]

    int t    = threadIdx.x;
    int lane = t & 31, wid = t >> 5;
    int mstrip = wid >> 1, nhalf = wid & 1;
    int gID = lane >> 2, tID = lane & 3;
    int r0t = mstrip * 16 + gID;
    int i0  = blockIdx.x * GM;

    if (t < 128) *(float4*)&as[t * 4] = *(const float4*)&a[t * 4];

    float acc[16][4];
#pragma unroll
    for (int n = 0; n < 16; n++)
#pragma unroll
        for (int u = 0; u < 4; u++) acc[n][u] = 0.f;

    stage_g(sbase, h, i0, 0, t);
    cp_commit();

    for (int c = 0; c < FIN / KC; c++) {
        int buf = c & 1;
        cp_wait<0>();
        __syncthreads();
        if (c + 1 < FIN / KC) {
            stage_g(sbase, h, i0, c + 1, t);
            cp_commit();
        }
        const float* hs = gsm + buf * HS_WORDS;
        const float* Wb = gsm + 2 * HS_WORDS + buf * GWTILE_WORDS;
#pragma unroll
        for (int k = 0; k < 8; k++) {
            int kc = tID + 8 * k;
            uint32_t a0 = tf32_bits(hs[(r0t)     * HS + kc]);
            uint32_t a1 = tf32_bits(hs[(r0t + 8) * HS + kc]);
            uint32_t a2 = tf32_bits(hs[(r0t)     * HS + kc + 4]);
            uint32_t a3 = tf32_bits(hs[(r0t + 8) * HS + kc + 4]);
            int krow = k * 8 + tID;
#pragma unroll
            for (int n = 0; n < 16; n++) {
                int n0 = nhalf * 128 + n * 8 + gID;
                uint32_t b0 = __float_as_uint(Wb[krow * GW_STRIDE + n0]);
                uint32_t b1 = __float_as_uint(Wb[(krow + 4) * GW_STRIDE + n0]);
                mma_tf32(acc[n], a0, a1, a2, a3, b0, b1);
            }
        }
        __syncthreads();
    }

    // epilogue: half WhhT (transposed [n][j]) + fused f1/f2 + block max(f2)
    float s1a = 0.f, s2a = 0.f, s1b = 0.f, s2b = 0.f;
    int cb = nhalf * 128 + tID * 2;
    int ia  = i0 + r0t, ib2 = i0 + r0t + 8;
#pragma unroll
    for (int n = 0; n < 16; n++) {
        int cc = cb + n * 8;
        d_WhhT[(size_t)cc * Nn + ia]        = __float2half(acc[n][0]);
        d_WhhT[(size_t)(cc + 1) * Nn + ia]  = __float2half(acc[n][1]);
        d_WhhT[(size_t)cc * Nn + ib2]       = __float2half(acc[n][2]);
        d_WhhT[(size_t)(cc + 1) * Nn + ib2] = __float2half(acc[n][3]);
        float a10 = as[cc], a11 = as[cc + 1];
        float a20 = as[256 + cc], a21 = as[256 + cc + 1];
        s1a += acc[n][0] * a10 + acc[n][1] * a11;
        s2a += acc[n][0] * a20 + acc[n][1] * a21;
        s1b += acc[n][2] * a10 + acc[n][3] * a11;
        s2b += acc[n][2] * a20 + acc[n][3] * a21;
    }
#pragma unroll
    for (int o = 1; o <= 2; o <<= 1) {
        s1a += __shfl_xor_sync(0xffffffffu, s1a, o);
        s2a += __shfl_xor_sync(0xffffffffu, s2a, o);
        s1b += __shfl_xor_sync(0xffffffffu, s1b, o);
        s2b += __shfl_xor_sync(0xffffffffu, s2b, o);
    }
    if (nhalf == 1 && tID == 0) {
        gsm[r0t]       = s1a;  gsm[64 + r0t]      = s2a;
        gsm[r0t + 8]   = s1b;  gsm[64 + r0t + 8]  = s2b;
    }
    __syncthreads();
    float mx = -3.0e38f;
    if (nhalf == 0 && tID == 0) {
        float f1t = s1a + gsm[r0t],     f2t = s2a + gsm[64 + r0t];
        float f1u = s1b + gsm[r0t + 8], f2u = s2b + gsm[64 + r0t + 8];
        d_f1[i0 + r0t]     = f1t;  d_f2[i0 + r0t]     = f2t;
        d_f1[i0 + r0t + 8] = f1u;  d_f2[i0 + r0t + 8] = f2u;
        mx = fmaxf(f2t, f2u);
    }
#pragma unroll
    for (int o = 16; o; o >>= 1)
        mx = fmaxf(mx, __shfl_xor_sync(0xffffffffu, mx, o));
    if (lane == 0) gsm[128 + wid] = mx;
    __syncthreads();
    if (t == 0) {
        float m = gsm[128];
#pragma unroll
        for (int w = 1; w < 8; w++) m = fmaxf(m, gsm[128 + w]);
        int b = __float_as_int(m);
        int key = b >= 0 ? b : (b ^ 0x7fffffff);
        atomicMax(&d_gmaxkey, key);
    }
}

// ---------------- factorized softmax weights ----------------
__global__ void pexp_kernel() {
    int i = blockIdx.x * 256 + threadIdx.x;
    int kk = d_gmaxkey;
    float gm = __int_as_float(kk >= 0 ? kk : (kk ^ 0x7fffffff));
    float f1 = d_f1[i], f2 = d_f2[i];
    float u  = f1 + gm;
    float m  = u > 0.f ? u : LALPHA * u;
    d_A[i] = __expf(u - m);
    d_C[i] = __expf(LALPHA * u - m);
    float v = f2 - gm;
    d_B[i] = __expf(v);
    d_D[i] = __expf(LALPHA * v);
}

// ---------------- staging helpers (cp.async) ----------------
__device__ __forceinline__ void stage_slot(uint32_t sbase, const int* adj,
                                           int s, int t) {
    int buf = s & 1;
    int ib  = s >> 7;
    int jg  = (s & (CPB - 1)) * KC;
    // WhT half tile [256 n][64 j], stride 72 halfs (144 B)
    uint32_t wb = sbase + (uint32_t)(buf * WHTILE_WORDS * 4);
#pragma unroll
    for (int u = 0; u < 4; u++) {
        int f = u * 512 + t;                  // 0..2047
        int row = f >> 3, seg = f & 7;        // 8 x 16B per row
        cp_async16(wb + (uint32_t)(row * 144 + seg * 16),
                   &d_WhhT[(size_t)row * Nn + jg + seg * 8]);
    }
    uint32_t ab = sbase + (uint32_t)((SM_ADJ + buf * ADJTILE_WORDS) * 4);
    const int* abase = adj + (size_t)ib * M_TILE * Nn + jg;
#pragma unroll
    for (int u = 0; u < 4; u++) {
        int f = u * 512 + t;
        int row = f >> 4, seg = (f & 15) << 2;
        cp_async16(ab + (uint32_t)((row * ADJ_STRIDE + seg) * 4),
                   abase + (size_t)row * Nn + seg);
    }
    if (t < 48) {
        uint32_t fb = sbase + (uint32_t)((SM_FBD + buf * 192 + t * 4) * 4);
        const float* src = (t < 16) ? &d_f2[jg + t * 4]
                         : (t < 32) ? &d_B[jg + (t - 16) * 4]
                                    : &d_D[jg + (t - 32) * 4];
        cp_async16(fb, src);
    }
}

// ---------------- fused attention @ Wh via mma.sync fp16 ----------------
// 148 CTAs x 512 threads = 16 warps: 8 m-strips x 2 n-halves, warp tile 16x128.
// 4 k16-steps x 16 n-tiles of m16n8k16; A-frags = inline P (half2),
// B-frags = one LDS.32 per half2 pair from WhT half tile (conflict-free).
__global__ void __launch_bounds__(512, 1) attn_mma(const int* __restrict__ adj) {
    extern __shared__ float sm[];
    uint32_t sbase = smem_u32(sm);

    int t    = threadIdx.x;
    int lane = t & 31, wid = t >> 5;
    int mstrip = wid >> 1, nhalf = wid & 1;
    int gID = lane >> 2, tID = lane & 3;
    int r0t = mstrip * 16 + gID;

    int s0 = (int)(((long long)blockIdx.x * TOTSLOT) / NCTA);
    int s1 = (int)(((long long)(blockIdx.x + 1) * TOTSLOT) / NCTA);

    float acc[16][4];
#pragma unroll
    for (int n = 0; n < 16; n++)
#pragma unroll
        for (int u = 0; u < 4; u++) acc[n][u] = 0.f;
    float ssum0 = 0.f, ssum1 = 0.f;

    float f1a = 0.f, Aa = 0.f, Ca = 0.f;
    float f1b = 0.f, Ab = 0.f, Cb = 0.f;
    int cur_ib = -1;

    stage_slot(sbase, adj, s0, t);
    cp_commit();

    for (int s = s0; s < s1; s++) {
        int ib = s >> 7;
        int buf = s & 1;

        if (ib != cur_ib) {
            if (cur_ib >= 0) {
                float sa = ssum0 + __shfl_xor_sync(0xffffffffu, ssum0, 1);
                sa += __shfl_xor_sync(0xffffffffu, sa, 2);
                float sb = ssum1 + __shfl_xor_sync(0xffffffffu, ssum1, 1);
                sb += __shfl_xor_sync(0xffffffffu, sb, 2);
                int base = cur_ib * M_TILE;
                if (tID == 0 && nhalf == 0) {
                    atomicAdd(&d_ssum[base + r0t], sa);
                    atomicAdd(&d_ssum[base + r0t + 8], sb);
                }
                float* np = &d_num[(size_t)(base) * FOUT];
                int cb = nhalf * 128 + tID * 2;
#pragma unroll
                for (int n = 0; n < 16; n++) {
                    int cc = cb + n * 8;
                    atomicAdd(&np[(size_t)r0t * FOUT + cc],       acc[n][0]);
                    atomicAdd(&np[(size_t)r0t * FOUT + cc + 1],   acc[n][1]);
                    atomicAdd(&np[(size_t)(r0t + 8) * FOUT + cc],     acc[n][2]);
                    atomicAdd(&np[(size_t)(r0t + 8) * FOUT + cc + 1], acc[n][3]);
                }
#pragma unroll
                for (int n = 0; n < 16; n++)
#pragma unroll
                    for (int u = 0; u < 4; u++) acc[n][u] = 0.f;
                ssum0 = 0.f; ssum1 = 0.f;
            }
            int base = ib * M_TILE;
            f1a = d_f1[base + r0t];     f1b = d_f1[base + r0t + 8];
            Aa  = d_A[base + r0t];      Ab  = d_A[base + r0t + 8];
            Ca  = d_C[base + r0t];      Cb  = d_C[base + r0t + 8];
            cur_ib = ib;
        }

        cp_wait<0>();
        __syncthreads();

        if (s + 1 < s1) {
            stage_slot(sbase, adj, s + 1, t);
            cp_commit();
        }

        const __half* WbH = (const __half*)(sm + buf * WHTILE_WORDS);
        const int*    adjS = (const int*)(sm + SM_ADJ + buf * ADJTILE_WORDS);
        const float*  fbd  = sm + SM_FBD + buf * 192;

#pragma unroll
        for (int k = 0; k < 4; k++) {
            int j0 = 2 * tID + 16 * k;      // even
            int j8 = j0 + 8;
            // adj pairs (int2, 8B-aligned)
            int2 adA0 = *(const int2*)&adjS[r0t * ADJ_STRIDE + j0];
            int2 adA8 = *(const int2*)&adjS[r0t * ADJ_STRIDE + j8];
            int2 adB0 = *(const int2*)&adjS[(r0t + 8) * ADJ_STRIDE + j0];
            int2 adB8 = *(const int2*)&adjS[(r0t + 8) * ADJ_STRIDE + j8];
            float2 f2v0 = *(const float2*)&fbd[j0];
            float2 f2v8 = *(const float2*)&fbd[j8];
            float2 Bv0  = *(const float2*)&fbd[64 + j0];
            float2 Bv8  = *(const float2*)&fbd[64 + j8];
            float2 Dv0  = *(const float2*)&fbd[128 + j0];
            float2 Dv8  = *(const float2*)&fbd[128 + j8];

            // row r0t (x) and r0t+8 (y), j = j0, j0+1, j8, j8+1
            float ex0 = f1a + f2v0.x, ex1 = f1a + f2v0.y;
            float ex8 = f1a + f2v8.x, ex9 = f1a + f2v8.y;
            float ey0 = f1b + f2v0.x, ey1 = f1b + f2v0.y;
            float ey8 = f1b + f2v8.x, ey9 = f1b + f2v8.y;
            float px0 = (adA0.x > 0) ? (ex0 > 0.f ? Aa * Bv0.x : Ca * Dv0.x) : 0.f;
            float px1 = (adA0.y > 0) ? (ex1 > 0.f ? Aa * Bv0.y : Ca * Dv0.y) : 0.f;
            float px8 = (adA8.x > 0) ? (ex8 > 0.f ? Aa * Bv8.x : Ca * Dv8.x) : 0.f;
            float px9 = (adA8.y > 0) ? (ex9 > 0.f ? Aa * Bv8.y : Ca * Dv8.y) : 0.f;
            float py0 = (adB0.x > 0) ? (ey0 > 0.f ? Ab * Bv0.x : Cb * Dv0.x) : 0.f;
            float py1 = (adB0.y > 0) ? (ey1 > 0.f ? Ab * Bv0.y : Cb * Dv0.y) : 0.f;
            float py8 = (adB8.x > 0) ? (ey8 > 0.f ? Ab * Bv8.x : Cb * Dv8.x) : 0.f;
            float py9 = (adB8.y > 0) ? (ey9 > 0.f ? Ab * Bv8.y : Cb * Dv8.y) : 0.f;
            if (nhalf == 0) {
                ssum0 += (px0 + px1) + (px8 + px9);
                ssum1 += (py0 + py1) + (py8 + py9);
            }
            __half2 h;
            h = __floats2half2_rn(px0, px1); uint32_t a0 = *(uint32_t*)&h;
            h = __floats2half2_rn(py0, py1); uint32_t a1 = *(uint32_t*)&h;
            h = __floats2half2_rn(px8, px9); uint32_t a2 = *(uint32_t*)&h;
            h = __floats2half2_rn(py8, py9); uint32_t a3 = *(uint32_t*)&h;

            int kh = 2 * tID + 16 * k;
#pragma unroll
            for (int n = 0; n < 16; n++) {
                int n0 = nhalf * 128 + n * 8 + gID;
                uint32_t b0 = *(const uint32_t*)&WbH[n0 * WT_STRIDE_H + kh];
                uint32_t b1 = *(const uint32_t*)&WbH[n0 * WT_STRIDE_H + kh + 8];
                mma_f16(acc[n], a0, a1, a2, a3, b0, b1);
            }
        }
    }

    {
        float sa = ssum0 + __shfl_xor_sync(0xffffffffu, ssum0, 1);
        sa += __shfl_xor_sync(0xffffffffu, sa, 2);
        float sb = ssum1 + __shfl_xor_sync(0xffffffffu, ssum1, 1);
        sb += __shfl_xor_sync(0xffffffffu, sb, 2);
        int base = cur_ib * M_TILE;
        if (tID == 0 && nhalf == 0) {
            atomicAdd(&d_ssum[base + r0t], sa);
            atomicAdd(&d_ssum[base + r0t + 8], sb);
        }
        float* np = &d_num[(size_t)(base) * FOUT];
        int cb = nhalf * 128 + tID * 2;
#pragma unroll
        for (int n = 0; n < 16; n++) {
            int cc = cb + n * 8;
            atomicAdd(&np[(size_t)r0t * FOUT + cc],       acc[n][0]);
            atomicAdd(&np[(size_t)r0t * FOUT + cc + 1],   acc[n][1]);
            atomicAdd(&np[(size_t)(r0t + 8) * FOUT + cc],     acc[n][2]);
            atomicAdd(&np[(size_t)(r0t + 8) * FOUT + cc + 1], acc[n][3]);
        }
    }
}

// ---------------- normalize + ELU (vectorized) ----------------
__global__ void elu_kernel(float* __restrict__ out) {
    int idx = blockIdx.x * 256 + threadIdx.x;     // one float4 per thread
    int row = idx >> 6;                           // 64 float4 per row
    float s = d_ssum[row];
    float4 v = *(const float4*)&d_num[(size_t)idx * 4];
    float4 o;
    float x;
    x = v.x / s; o.x = x > 0.f ? x : expm1f(x);
    x = v.y / s; o.y = x > 0.f ? x : expm1f(x);
    x = v.z / s; o.z = x > 0.f ? x : expm1f(x);
    x = v.w / s; o.w = x > 0.f ? x : expm1f(x);
    *(float4*)&out[(size_t)idx * 4] = o;
}

extern "C" void kernel_launch(void* const* d_in, const int* in_sizes, int n_in,
                              void* d_out, int out_size) {
    const float* h   = (const float*)d_in[0];
    const int*   adj = (const int*)d_in[1];
    const float* W   = (const float*)d_in[2];
    const float* a   = (const float*)d_in[3];
    float* out = (float*)d_out;

    cudaFuncSetAttribute(attn_mma, cudaFuncAttributeMaxDynamicSharedMemorySize, SMEM_DYN);
    cudaFuncSetAttribute(gemm_wh_mma, cudaFuncAttributeMaxDynamicSharedMemorySize, GSMEM_DYN);

    init_kernel<<<(Nn * FOUT) / 1024, 256>>>(W);
    gemm_wh_mma<<<Nn / GM, 256, GSMEM_DYN>>>(h, a);
    pexp_kernel<<<Nn / 256, 256>>>();
    attn_mma<<<NCTA, 512, SMEM_DYN>>>(adj);
    elu_kernel<<<(Nn * FOUT) / 1024, 256>>>(out);
}

// round 14
// speedup vs baseline: 1.5317x; 1.0117x over previous
#include <cuda_runtime.h>
#include <cuda_fp16.h>
#include <cstdint>

#define Nn     8192
#define FIN    512
#define FOUT   256
#define LALPHA 0.2f
#define M_TILE 128
#define KC     64
#define NBLK   (Nn / M_TILE)          // 64 row blocks
#define CPB    (Nn / KC)              // 128 chunks per row block
#define TOTSLOT (NBLK * CPB)          // 8192
#define NCTA   148

// attn smem layout (words)
#define WT_STRIDE_H 72                // WhT half tile j-stride (halfs) = 36 words
#define WHTILE_WORDS (FOUT * (WT_STRIDE_H / 2))   // 256*36 = 9216
#define ADJ_STRIDE 68
#define ADJTILE_WORDS (M_TILE * ADJ_STRIDE)       // 8704
#define SM_ADJ (2 * WHTILE_WORDS)                 // 18432
#define SM_FBD (SM_ADJ + 2 * ADJTILE_WORDS)       // 35840
#define SMEM_DYN ((SM_FBD + 2 * 192) * 4)         // 144896 B

// gemm_wh_mma tiles
#define GW_STRIDE 264
#define GWTILE_WORDS (KC * GW_STRIDE)             // 16896
#define GM      64
#define HS      68
#define HS_WORDS (GM * HS)                        // 4352
#define GSM_A   (2 * HS_WORDS + 2 * GWTILE_WORDS)
#define GSMEM_DYN ((GSM_A + 512) * 4)             // 172032 B

// ---------------- scratch (device globals: allowed) ----------------
__device__ __half d_WhhT[(size_t)FOUT * Nn];         // 4 MB half, [n][j]
__device__ float d_Wr[(size_t)FIN * FOUT];           // tf32-rounded W
__device__ float d_f1[Nn];
__device__ float d_f2[Nn];
__device__ float d_A[Nn];
__device__ float d_C[Nn];
__device__ float d_B[Nn];
__device__ float d_D[Nn];
__device__ int   d_gmaxkey;
__device__ float d_num[(size_t)Nn * FOUT];           // 8 MB (atomic accum)
__device__ float d_ssum[Nn];

__device__ __forceinline__ uint32_t tf32_bits(float x) {
    uint32_t r; asm("cvt.rna.tf32.f32 %0, %1;" : "=r"(r) : "f"(x)); return r;
}
__device__ __forceinline__ void mma_tf32(float* d, uint32_t a0, uint32_t a1,
                                         uint32_t a2, uint32_t a3,
                                         uint32_t b0, uint32_t b1) {
    asm volatile(
        "mma.sync.aligned.m16n8k8.row.col.f32.tf32.tf32.f32 "
        "{%0,%1,%2,%3}, {%4,%5,%6,%7}, {%8,%9}, {%0,%1,%2,%3};"
        : "+f"(d[0]), "+f"(d[1]), "+f"(d[2]), "+f"(d[3])
        : "r"(a0), "r"(a1), "r"(a2), "r"(a3), "r"(b0), "r"(b1));
}
__device__ __forceinline__ void mma_f16(float* d, uint32_t a0, uint32_t a1,
                                        uint32_t a2, uint32_t a3,
                                        uint32_t b0, uint32_t b1) {
    asm volatile(
        "mma.sync.aligned.m16n8k16.row.col.f32.f16.f16.f32 "
        "{%0,%1,%2,%3}, {%4,%5,%6,%7}, {%8,%9}, {%0,%1,%2,%3};"
        : "+f"(d[0]), "+f"(d[1]), "+f"(d[2]), "+f"(d[3])
        : "r"(a0), "r"(a1), "r"(a2), "r"(a3), "r"(b0), "r"(b1));
}
__device__ __forceinline__ uint32_t smem_u32(const void* p) {
    uint32_t a;
    asm("{ .reg .u64 t; cvta.to.shared.u64 t, %1; cvt.u32.u64 %0, t; }"
        : "=r"(a) : "l"(p));
    return a;
}
__device__ __forceinline__ void cp_async16(uint32_t sa, const void* g) {
    asm volatile("cp.async.ca.shared.global [%0], [%1], 16;" :: "r"(sa), "l"(g) : "memory");
}
__device__ __forceinline__ void cp_commit() {
    asm volatile("cp.async.commit_group;" ::: "memory");
}
template <int N> __device__ __forceinline__ void cp_wait() {
    asm volatile("cp.async.wait_group %0;" :: "n"(N) : "memory");
}

// ---------------- init: zero accumulators + round W ----------------
__global__ void init_kernel(const float* __restrict__ W) {
    if (blockIdx.x == 0 && threadIdx.x == 0) d_gmaxkey = (int)0x80000000;
    size_t i = ((size_t)blockIdx.x * 256 + threadIdx.x) * 4;
    *(float4*)&d_num[i] = make_float4(0.f, 0.f, 0.f, 0.f);
    if (i < Nn)
        *(float4*)&d_ssum[i] = make_float4(0.f, 0.f, 0.f, 0.f);
    if (i < (size_t)FIN * FOUT) {
        float4 v = *(const float4*)&W[i];
        float4 o;
        o.x = __uint_as_float(tf32_bits(v.x));
        o.y = __uint_as_float(tf32_bits(v.y));
        o.z = __uint_as_float(tf32_bits(v.z));
        o.w = __uint_as_float(tf32_bits(v.w));
        *(float4*)&d_Wr[i] = o;
    }
}

// ---------------- Wh = h @ W via mma.sync tf32 (+ fused f1/f2/max) ----------------
__device__ __forceinline__ void stage_g(uint32_t sbase, const float* __restrict__ h,
                                        int i0, int c, int t) {
    int buf = c & 1;
    int k0  = c * KC;
    uint32_t hb = sbase + (uint32_t)(buf * HS_WORDS * 4);
#pragma unroll
    for (int u = 0; u < 4; u++) {
        int f = u * 256 + t;
        int row = f >> 4, seg = (f & 15) << 2;
        cp_async16(hb + (uint32_t)((row * HS + seg) * 4),
                   &h[(size_t)(i0 + row) * FIN + k0 + seg]);
    }
    uint32_t wb = sbase + (uint32_t)((2 * HS_WORDS + buf * GWTILE_WORDS) * 4);
#pragma unroll
    for (int u = 0; u < 16; u++) {
        int f = u * 256 + t;
        int row = f >> 6, c4 = (f & 63) << 2;
        cp_async16(wb + (uint32_t)((row * GW_STRIDE + c4) * 4),
                   &d_Wr[(size_t)(k0 + row) * FOUT + c4]);
    }
}

__global__ void __launch_bounds__(256, 1) gemm_wh_mma(const float* __restrict__ h,
                                                      const float* __restrict__ a) {
    extern __shared__ float gsm[];
    uint32_t sbase = smem_u32(gsm);
    float* as = gsm + GSM_A;   // a1[256] then a2[256]

    int t    = threadIdx.x;
    int lane = t & 31, wid = t >> 5;
    int mstrip = wid >> 1, nhalf = wid & 1;
    int gID = lane >> 2, tID = lane & 3;
    int r0t = mstrip * 16 + gID;
    int i0  = blockIdx.x * GM;

    if (t < 128) *(float4*)&as[t * 4] = *(const float4*)&a[t * 4];

    float acc[16][4];
#pragma unroll
    for (int n = 0; n < 16; n++)
#pragma unroll
        for (int u = 0; u < 4; u++) acc[n][u] = 0.f;

    stage_g(sbase, h, i0, 0, t);
    cp_commit();

    for (int c = 0; c < FIN / KC; c++) {
        int buf = c & 1;
        cp_wait<0>();
        __syncthreads();
        if (c + 1 < FIN / KC) {
            stage_g(sbase, h, i0, c + 1, t);
            cp_commit();
        }
        const float* hs = gsm + buf * HS_WORDS;
        const float* Wb = gsm + 2 * HS_WORDS + buf * GWTILE_WORDS;
#pragma unroll
        for (int k = 0; k < 8; k++) {
            int kc = tID + 8 * k;
            uint32_t a0 = tf32_bits(hs[(r0t)     * HS + kc]);
            uint32_t a1 = tf32_bits(hs[(r0t + 8) * HS + kc]);
            uint32_t a2 = tf32_bits(hs[(r0t)     * HS + kc + 4]);
            uint32_t a3 = tf32_bits(hs[(r0t + 8) * HS + kc + 4]);
            int krow = k * 8 + tID;
#pragma unroll
            for (int n = 0; n < 16; n++) {
                int n0 = nhalf * 128 + n * 8 + gID;
                uint32_t b0 = __float_as_uint(Wb[krow * GW_STRIDE + n0]);
                uint32_t b1 = __float_as_uint(Wb[(krow + 4) * GW_STRIDE + n0]);
                mma_tf32(acc[n], a0, a1, a2, a3, b0, b1);
            }
        }
        __syncthreads();
    }

    // epilogue: half WhhT (transposed [n][j]) + fused f1/f2 + block max(f2)
    float s1a = 0.f, s2a = 0.f, s1b = 0.f, s2b = 0.f;
    int cb = nhalf * 128 + tID * 2;
    int ia  = i0 + r0t, ib2 = i0 + r0t + 8;
#pragma unroll
    for (int n = 0; n < 16; n++) {
        int cc = cb + n * 8;
        d_WhhT[(size_t)cc * Nn + ia]        = __float2half(acc[n][0]);
        d_WhhT[(size_t)(cc + 1) * Nn + ia]  = __float2half(acc[n][1]);
        d_WhhT[(size_t)cc * Nn + ib2]       = __float2half(acc[n][2]);
        d_WhhT[(size_t)(cc + 1) * Nn + ib2] = __float2half(acc[n][3]);
        float a10 = as[cc], a11 = as[cc + 1];
        float a20 = as[256 + cc], a21 = as[256 + cc + 1];
        s1a += acc[n][0] * a10 + acc[n][1] * a11;
        s2a += acc[n][0] * a20 + acc[n][1] * a21;
        s1b += acc[n][2] * a10 + acc[n][3] * a11;
        s2b += acc[n][2] * a20 + acc[n][3] * a21;
    }
#pragma unroll
    for (int o = 1; o <= 2; o <<= 1) {
        s1a += __shfl_xor_sync(0xffffffffu, s1a, o);
        s2a += __shfl_xor_sync(0xffffffffu, s2a, o);
        s1b += __shfl_xor_sync(0xffffffffu, s1b, o);
        s2b += __shfl_xor_sync(0xffffffffu, s2b, o);
    }
    if (nhalf == 1 && tID == 0) {
        gsm[r0t]       = s1a;  gsm[64 + r0t]      = s2a;
        gsm[r0t + 8]   = s1b;  gsm[64 + r0t + 8]  = s2b;
    }
    __syncthreads();
    float mx = -3.0e38f;
    if (nhalf == 0 && tID == 0) {
        float f1t = s1a + gsm[r0t],     f2t = s2a + gsm[64 + r0t];
        float f1u = s1b + gsm[r0t + 8], f2u = s2b + gsm[64 + r0t + 8];
        d_f1[i0 + r0t]     = f1t;  d_f2[i0 + r0t]     = f2t;
        d_f1[i0 + r0t + 8] = f1u;  d_f2[i0 + r0t + 8] = f2u;
        mx = fmaxf(f2t, f2u);
    }
#pragma unroll
    for (int o = 16; o; o >>= 1)
        mx = fmaxf(mx, __shfl_xor_sync(0xffffffffu, mx, o));
    if (lane == 0) gsm[128 + wid] = mx;
    __syncthreads();
    if (t == 0) {
        float m = gsm[128];
#pragma unroll
        for (int w = 1; w < 8; w++) m = fmaxf(m, gsm[128 + w]);
        int b = __float_as_int(m);
        int key = b >= 0 ? b : (b ^ 0x7fffffff);
        atomicMax(&d_gmaxkey, key);
    }
}

// ---------------- factorized softmax weights ----------------
__global__ void pexp_kernel() {
    int i = blockIdx.x * 256 + threadIdx.x;
    int kk = d_gmaxkey;
    float gm = __int_as_float(kk >= 0 ? kk : (kk ^ 0x7fffffff));
    float f1 = d_f1[i], f2 = d_f2[i];
    float u  = f1 + gm;
    float m  = u > 0.f ? u : LALPHA * u;
    d_A[i] = __expf(u - m);
    d_C[i] = __expf(LALPHA * u - m);
    float v = f2 - gm;
    d_B[i] = __expf(v);
    d_D[i] = __expf(LALPHA * v);
}

// ---------------- staging helpers (cp.async) ----------------
__device__ __forceinline__ void stage_slot(uint32_t sbase, const int* adj,
                                           int s, int t) {
    int buf = s & 1;
    int ib  = s >> 7;
    int jg  = (s & (CPB - 1)) * KC;
    // WhT half tile [256 n][64 j], stride 72 halfs (144 B)
    uint32_t wb = sbase + (uint32_t)(buf * WHTILE_WORDS * 4);
#pragma unroll
    for (int u = 0; u < 4; u++) {
        int f = u * 512 + t;                  // 0..2047
        int row = f >> 3, seg = f & 7;        // 8 x 16B per row
        cp_async16(wb + (uint32_t)(row * 144 + seg * 16),
                   &d_WhhT[(size_t)row * Nn + jg + seg * 8]);
    }
    uint32_t ab = sbase + (uint32_t)((SM_ADJ + buf * ADJTILE_WORDS) * 4);
    const int* abase = adj + (size_t)ib * M_TILE * Nn + jg;
#pragma unroll
    for (int u = 0; u < 4; u++) {
        int f = u * 512 + t;
        int row = f >> 4, seg = (f & 15) << 2;
        cp_async16(ab + (uint32_t)((row * ADJ_STRIDE + seg) * 4),
                   abase + (size_t)row * Nn + seg);
    }
    if (t < 48) {
        uint32_t fb = sbase + (uint32_t)((SM_FBD + buf * 192 + t * 4) * 4);
        const float* src = (t < 16) ? &d_f2[jg + t * 4]
                         : (t < 32) ? &d_B[jg + (t - 16) * 4]
                                    : &d_D[jg + (t - 32) * 4];
        cp_async16(fb, src);
    }
}

// ---------------- fused attention @ Wh via mma.sync fp16 + ldmatrix ----------------
// 148 CTAs x 512 threads = 16 warps: 8 m-strips x 2 n-halves, warp tile 16x128.
// 4 k16-steps x 8 n-pairs; B-frags for 2 n-tiles per ldmatrix.m8n8.x4 (LDSM).
__global__ void __launch_bounds__(512, 1) attn_mma(const int* __restrict__ adj) {
    extern __shared__ float sm[];
    uint32_t sbase = smem_u32(sm);

    int t    = threadIdx.x;
    int lane = t & 31, wid = t >> 5;
    int mstrip = wid >> 1, nhalf = wid & 1;
    int gID = lane >> 2, tID = lane & 3;
    int r0t = mstrip * 16 + gID;

    // ldmatrix lane address: quadrants q0:(n=lr,k+0) q1:(n=lr,k+8) q2:(n=8+lr,k+0) q3:(n=8+lr,k+8)
    int lq = lane >> 3, lr = lane & 7;
    int n_l  = ((lq >> 1) << 3) + lr;          // 0..15 within n-pair
    int kc_l = (lq & 1) << 3;                  // 0 or 8 (halfs)
    uint32_t lm_lane_off =
        (uint32_t)(((nhalf * 128 + n_l) * WT_STRIDE_H + kc_l) * 2); // bytes

    int s0 = (int)(((long long)blockIdx.x * TOTSLOT) / NCTA);
    int s1 = (int)(((long long)(blockIdx.x + 1) * TOTSLOT) / NCTA);

    float acc[16][4];
#pragma unroll
    for (int n = 0; n < 16; n++)
#pragma unroll
        for (int u = 0; u < 4; u++) acc[n][u] = 0.f;
    float ssum0 = 0.f, ssum1 = 0.f;

    float f1a = 0.f, Aa = 0.f, Ca = 0.f;
    float f1b = 0.f, Ab = 0.f, Cb = 0.f;
    int cur_ib = -1;

    stage_slot(sbase, adj, s0, t);
    cp_commit();

    for (int s = s0; s < s1; s++) {
        int ib = s >> 7;
        int buf = s & 1;

        if (ib != cur_ib) {
            if (cur_ib >= 0) {
                float sa = ssum0 + __shfl_xor_sync(0xffffffffu, ssum0, 1);
                sa += __shfl_xor_sync(0xffffffffu, sa, 2);
                float sb = ssum1 + __shfl_xor_sync(0xffffffffu, ssum1, 1);
                sb += __shfl_xor_sync(0xffffffffu, sb, 2);
                int base = cur_ib * M_TILE;
                if (tID == 0 && nhalf == 0) {
                    atomicAdd(&d_ssum[base + r0t], sa);
                    atomicAdd(&d_ssum[base + r0t + 8], sb);
                }
                float* np = &d_num[(size_t)(base) * FOUT];
                int cb = nhalf * 128 + tID * 2;
#pragma unroll
                for (int n = 0; n < 16; n++) {
                    int cc = cb + n * 8;
                    atomicAdd(&np[(size_t)r0t * FOUT + cc],       acc[n][0]);
                    atomicAdd(&np[(size_t)r0t * FOUT + cc + 1],   acc[n][1]);
                    atomicAdd(&np[(size_t)(r0t + 8) * FOUT + cc],     acc[n][2]);
                    atomicAdd(&np[(size_t)(r0t + 8) * FOUT + cc + 1], acc[n][3]);
                }
#pragma unroll
                for (int n = 0; n < 16; n++)
#pragma unroll
                    for (int u = 0; u < 4; u++) acc[n][u] = 0.f;
                ssum0 = 0.f; ssum1 = 0.f;
            }
            int base = ib * M_TILE;
            f1a = d_f1[base + r0t];     f1b = d_f1[base + r0t + 8];
            Aa  = d_A[base + r0t];      Ab  = d_A[base + r0t + 8];
            Ca  = d_C[base + r0t];      Cb  = d_C[base + r0t + 8];
            cur_ib = ib;
        }

        cp_wait<0>();
        __syncthreads();

        if (s + 1 < s1) {
            stage_slot(sbase, adj, s + 1, t);
            cp_commit();
        }

        uint32_t lm_base = sbase + (uint32_t)(buf * WHTILE_WORDS * 4) + lm_lane_off;
        const int*    adjS = (const int*)(sm + SM_ADJ + buf * ADJTILE_WORDS);
        const float*  fbd  = sm + SM_FBD + buf * 192;

#pragma unroll
        for (int k = 0; k < 4; k++) {
            int j0 = 2 * tID + 16 * k;      // even
            int j8 = j0 + 8;
            int2 adA0 = *(const int2*)&adjS[r0t * ADJ_STRIDE + j0];
            int2 adA8 = *(const int2*)&adjS[r0t * ADJ_STRIDE + j8];
            int2 adB0 = *(const int2*)&adjS[(r0t + 8) * ADJ_STRIDE + j0];
            int2 adB8 = *(const int2*)&adjS[(r0t + 8) * ADJ_STRIDE + j8];
            float2 f2v0 = *(const float2*)&fbd[j0];
            float2 f2v8 = *(const float2*)&fbd[j8];
            float2 Bv0  = *(const float2*)&fbd[64 + j0];
            float2 Bv8  = *(const float2*)&fbd[64 + j8];
            float2 Dv0  = *(const float2*)&fbd[128 + j0];
            float2 Dv8  = *(const float2*)&fbd[128 + j8];

            float ex0 = f1a + f2v0.x, ex1 = f1a + f2v0.y;
            float ex8 = f1a + f2v8.x, ex9 = f1a + f2v8.y;
            float ey0 = f1b + f2v0.x, ey1 = f1b + f2v0.y;
            float ey8 = f1b + f2v8.x, ey9 = f1b + f2v8.y;
            float px0 = (adA0.x > 0) ? (ex0 > 0.f ? Aa * Bv0.x : Ca * Dv0.x) : 0.f;
            float px1 = (adA0.y > 0) ? (ex1 > 0.f ? Aa * Bv0.y : Ca * Dv0.y) : 0.f;
            float px8 = (adA8.x > 0) ? (ex8 > 0.f ? Aa * Bv8.x : Ca * Dv8.x) : 0.f;
            float px9 = (adA8.y > 0) ? (ex9 > 0.f ? Aa * Bv8.y : Ca * Dv8.y) : 0.f;
            float py0 = (adB0.x > 0) ? (ey0 > 0.f ? Ab * Bv0.x : Cb * Dv0.x) : 0.f;
            float py1 = (adB0.y > 0) ? (ey1 > 0.f ? Ab * Bv0.y : Cb * Dv0.y) : 0.f;
            float py8 = (adB8.x > 0) ? (ey8 > 0.f ? Ab * Bv8.x : Cb * Dv8.x) : 0.f;
            float py9 = (adB8.y > 0) ? (ey9 > 0.f ? Ab * Bv8.y : Cb * Dv8.y) : 0.f;
            if (nhalf == 0) {
                ssum0 += (px0 + px1) + (px8 + px9);
                ssum1 += (py0 + py1) + (py8 + py9);
            }
            __half2 hh;
            hh = __floats2half2_rn(px0, px1); uint32_t a0 = *(uint32_t*)&hh;
            hh = __floats2half2_rn(py0, py1); uint32_t a1 = *(uint32_t*)&hh;
            hh = __floats2half2_rn(px8, px9); uint32_t a2 = *(uint32_t*)&hh;
            hh = __floats2half2_rn(py8, py9); uint32_t a3 = *(uint32_t*)&hh;

            uint32_t lmk = lm_base + (uint32_t)(k * 32);   // 16 halfs per k-step
#pragma unroll
            for (int p = 0; p < 8; p++) {
                uint32_t b00, b01, b10, b11;
                asm volatile(
                    "ldmatrix.sync.aligned.m8n8.x4.shared.b16 {%0,%1,%2,%3}, [%4];"
                    : "=r"(b00), "=r"(b01), "=r"(b10), "=r"(b11)
                    : "r"(lmk + (uint32_t)(p * 16 * WT_STRIDE_H * 2)));
                mma_f16(acc[2 * p],     a0, a1, a2, a3, b00, b01);
                mma_f16(acc[2 * p + 1], a0, a1, a2, a3, b10, b11);
            }
        }
    }

    {
        float sa = ssum0 + __shfl_xor_sync(0xffffffffu, ssum0, 1);
        sa += __shfl_xor_sync(0xffffffffu, sa, 2);
        float sb = ssum1 + __shfl_xor_sync(0xffffffffu, ssum1, 1);
        sb += __shfl_xor_sync(0xffffffffu, sb, 2);
        int base = cur_ib * M_TILE;
        if (tID == 0 && nhalf == 0) {
            atomicAdd(&d_ssum[base + r0t], sa);
            atomicAdd(&d_ssum[base + r0t + 8], sb);
        }
        float* np = &d_num[(size_t)(base) * FOUT];
        int cb = nhalf * 128 + tID * 2;
#pragma unroll
        for (int n = 0; n < 16; n++) {
            int cc = cb + n * 8;
            atomicAdd(&np[(size_t)r0t * FOUT + cc],       acc[n][0]);
            atomicAdd(&np[(size_t)r0t * FOUT + cc + 1],   acc[n][1]);
            atomicAdd(&np[(size_t)(r0t + 8) * FOUT + cc],     acc[n][2]);
            atomicAdd(&np[(size_t)(r0t + 8) * FOUT + cc + 1], acc[n][3]);
        }
    }
}

// ---------------- normalize + ELU (vectorized) ----------------
__global__ void elu_kernel(float* __restrict__ out) {
    int idx = blockIdx.x * 256 + threadIdx.x;     // one float4 per thread
    int row = idx >> 6;                           // 64 float4 per row
    float s = d_ssum[row];
    float4 v = *(const float4*)&d_num[(size_t)idx * 4];
    float4 o;
    float x;
    x = v.x / s; o.x = x > 0.f ? x : expm1f(x);
    x = v.y / s; o.y = x > 0.f ? x : expm1f(x);
    x = v.z / s; o.z = x > 0.f ? x : expm1f(x);
    x = v.w / s; o.w = x > 0.f ? x : expm1f(x);
    *(float4*)&out[(size_t)idx * 4] = o;
}

extern "C" void kernel_launch(void* const* d_in, const int* in_sizes, int n_in,
                              void* d_out, int out_size) {
    const float* h   = (const float*)d_in[0];
    const int*   adj = (const int*)d_in[1];
    const float* W   = (const float*)d_in[2];
    const float* a   = (const float*)d_in[3];
    float* out = (float*)d_out;

    cudaFuncSetAttribute(attn_mma, cudaFuncAttributeMaxDynamicSharedMemorySize, SMEM_DYN);
    cudaFuncSetAttribute(gemm_wh_mma, cudaFuncAttributeMaxDynamicSharedMemorySize, GSMEM_DYN);

    init_kernel<<<(Nn * FOUT) / 1024, 256>>>(W);
    gemm_wh_mma<<<Nn / GM, 256, GSMEM_DYN>>>(h, a);
    pexp_kernel<<<Nn / 256, 256>>>();
    attn_mma<<<NCTA, 512, SMEM_DYN>>>(adj);
    elu_kernel<<<(Nn * FOUT) / 1024, 256>>>(out);
}